// round 3
// baseline (speedup 1.0000x reference)
#include <cuda_runtime.h>
#include <math_constants.h>

#define BB 8
#define CC 256
#define HH 128
#define WW 128
#define HW (HH*WW)
#define TOPK 10
#define THRESH 0.5f
#define MARGIN 0.5f
#define EPSV 1e-8f
#define NMAPS 16
#define CAND_CAP 3072          // expected ~1850 strict 3x3 maxima; huge margin
#define CTAS_PER_MAP 32
#define NTHREADS 128

// scratch (no allocations allowed); counters self-reset -> replay-safe
__device__ float    g_intensity[NMAPS][HW];
__device__ float    g_topk_val[NMAPS][TOPK];
__device__ int      g_topk_idx[NMAPS][TOPK];
__device__ float    g_losses[BB];
__device__ unsigned g_map_cnt[NMAPS];
__device__ unsigned g_samp_cnt[BB];
__device__ unsigned g_done_cnt;

__global__ void __launch_bounds__(NTHREADS) fused_kernel(
    const float* __restrict__ det, const float* __restrict__ loc,
    float* __restrict__ out)
{
    // 24KB static smem: candidate list, later aliased as feature tiles
    __shared__ float s_cval[CAND_CAP];          // 12KB
    __shared__ int   s_cidx[CAND_CAP];          // 12KB
    float (*df)[CC] = (float(*)[CC])s_cval;     // 10*256*4 = 10KB
    float (*lf)[CC] = (float(*)[CC])((char*)s_cval + TOPK * CC * 4); // next 10KB

    __shared__ unsigned s_flag;
    __shared__ int s_cn;
    __shared__ float s_na[TOPK], s_nb[TOPK], s_ws[4];

    const int tid = threadIdx.x;                 // 0..127
    const int bid = blockIdx.x;                  // 0..511
    const int m   = bid / CTAS_PER_MAP;          // map 0..15 (0..7 det, 8..15 loc)
    const int sl  = bid % CTAS_PER_MAP;          // slice within map
    const int t   = m >> 3;
    const int b   = m & 7;

    // ============ Phase A: intensity slice (268MB HBM stream) ===============
    {
        const float* src = (t == 0) ? det : loc;
        const int g = sl * NTHREADS + tid;       // 0..4095 float4 group
        const float4* base = ((const float4*)(src + (size_t)b * CC * HW)) + g;
        float a0 = 0.f, a1 = 0.f, a2 = 0.f, a3 = 0.f;
        #pragma unroll 8
        for (int c = 0; c < CC; c++) {
            float4 v = __ldcs(base + c * (HW / 4));
            a0 = fmaf(v.x, v.x, a0);
            a1 = fmaf(v.y, v.y, a1);
            a2 = fmaf(v.z, v.z, a2);
            a3 = fmaf(v.w, v.w, a3);
        }
        float4 o;
        o.x = sqrtf(a0); o.y = sqrtf(a1); o.z = sqrtf(a2); o.w = sqrtf(a3);
        ((float4*)g_intensity[m])[g] = o;
    }

    __syncthreads();
    if (tid == 0) {
        __threadfence();
        unsigned old = atomicAdd(&g_map_cnt[m], 1u);
        if (old == CTAS_PER_MAP - 1) g_map_cnt[m] = 0u;  // reset for replay
        s_flag = (old == CTAS_PER_MAP - 1);
        s_cn = 0;
    }
    __syncthreads();
    if (!s_flag) return;       // only the last CTA per map continues

    // ============ Phase B: 3x3 strict maxima + top-10 for map m =============
    __threadfence();           // acquire published intensity
    const float* gi = g_intensity[m];

    for (int i = tid; i < HW; i += NTHREADS) {
        float v = __ldg(&gi[i]);
        if (v > THRESH) {
            int y = i >> 7, x = i & 127;
            bool peak = true;
            #pragma unroll
            for (int dy = -1; dy <= 1; dy++) {
                int yy = y + dy;
                if (yy < 0 || yy >= HH) continue;
                #pragma unroll
                for (int dx = -1; dx <= 1; dx++) {
                    int xx = x + dx;
                    if (xx < 0 || xx >= WW) continue;
                    if (__ldg(&gi[(yy << 7) + xx]) > v) peak = false;
                }
            }
            if (peak) {
                int p = atomicAdd(&s_cn, 1);
                if (p < CAND_CAP) { s_cval[p] = v; s_cidx[p] = i; }
            }
        }
    }
    __syncthreads();

    // warp 0: 10 argmax passes (value desc, index asc tie-break = lax.top_k)
    if (tid < 32) {
        int n = min(s_cn, CAND_CAP);
        for (int k = 0; k < TOPK; k++) {
            float bv = -CUDART_INF_F; int bi = 0x7fffffff; int bp = -1;
            for (int p = tid; p < n; p += 32) {
                float v = s_cval[p]; int i = s_cidx[p];
                if (v > bv || (v == bv && i < bi)) { bv = v; bi = i; bp = p; }
            }
            #pragma unroll
            for (int o = 16; o > 0; o >>= 1) {
                float v2 = __shfl_down_sync(0xffffffffu, bv, o);
                int   i2 = __shfl_down_sync(0xffffffffu, bi, o);
                int   p2 = __shfl_down_sync(0xffffffffu, bp, o);
                if (v2 > bv || (v2 == bv && i2 < bi)) { bv = v2; bi = i2; bp = p2; }
            }
            bp = __shfl_sync(0xffffffffu, bp, 0);
            if (tid == 0) {
                g_topk_val[m][k] = bv;             // -inf when no candidate
                g_topk_idx[m][k] = (bp >= 0) ? bi : 0;
                if (bp >= 0) s_cval[bp] = -CUDART_INF_F;
            }
            __syncwarp();
        }
    }
    __syncthreads();
    if (tid == 0) {
        __threadfence();
        unsigned old = atomicAdd(&g_samp_cnt[b], 1u);
        if (old == 1u) g_samp_cnt[b] = 0u;         // reset for replay
        s_flag = (old == 1u);
    }
    __syncthreads();
    if (!s_flag) return;       // only 2nd-finished map of this sample continues

    // ============ Phase C: cosine-sim loss for sample b =====================
    __threadfence();
    float dkv[TOPK], lkv[TOPK];
    int   dki[TOPK], lki[TOPK];
    #pragma unroll
    for (int k = 0; k < TOPK; k++) {
        dkv[k] = __ldcg(&g_topk_val[b][k]);
        dki[k] = __ldcg(&g_topk_idx[b][k]);
        lkv[k] = __ldcg(&g_topk_val[8 + b][k]);
        lki[k] = __ldcg(&g_topk_idx[8 + b][k]);
    }
    __syncthreads();           // candidate smem dead before aliasing overwrite

    // gather features: 128 threads x 2 channels each
    {
        const float* dbase = det + (size_t)b * CC * HW;
        const float* lbase = loc + (size_t)b * CC * HW;
        #pragma unroll
        for (int k = 0; k < TOPK; k++) {
            int c0 = tid, c1 = tid + NTHREADS;
            df[k][c0] = __ldg(&dbase[(size_t)c0 * HW + dki[k]]);
            df[k][c1] = __ldg(&dbase[(size_t)c1 * HW + dki[k]]);
            lf[k][c0] = __ldg(&lbase[(size_t)c0 * HW + lki[k]]);
            lf[k][c1] = __ldg(&lbase[(size_t)c1 * HW + lki[k]]);
        }
    }
    __syncthreads();

    const int lane = tid & 31, w = tid >> 5;       // 4 warps
    for (int k = w; k < TOPK; k += 4) {
        float sa = 0.f, sb = 0.f;
        for (int c = lane; c < CC; c += 32) {
            sa = fmaf(df[k][c], df[k][c], sa);
            sb = fmaf(lf[k][c], lf[k][c], sb);
        }
        #pragma unroll
        for (int o = 16; o > 0; o >>= 1) {
            sa += __shfl_down_sync(0xffffffffu, sa, o);
            sb += __shfl_down_sync(0xffffffffu, sb, o);
        }
        if (lane == 0) {
            s_na[k] = fmaxf(sqrtf(sa), EPSV);
            s_nb[k] = fmaxf(sqrtf(sb), EPSV);
        }
    }
    __syncthreads();

    float lsum = 0.f;
    for (int p = w; p < TOPK * TOPK; p += 4) {
        int i = p / TOPK, j = p % TOPK;
        float dot = 0.f;
        for (int c = lane; c < CC; c += 32) dot = fmaf(df[i][c], lf[j][c], dot);
        #pragma unroll
        for (int o = 16; o > 0; o >>= 1)
            dot += __shfl_down_sync(0xffffffffu, dot, o);
        if (lane == 0 && dkv[i] > -CUDART_INF_F && lkv[j] > -CUDART_INF_F)
            lsum += fmaxf(dot / (s_na[i] * s_nb[j]) - MARGIN, 0.f);
    }
    if (lane == 0) s_ws[w] = lsum;
    __syncthreads();

    if (tid == 0) {
        int nd = 0, nl = 0;
        #pragma unroll
        for (int k = 0; k < TOPK; k++) {
            nd += (dkv[k] > -CUDART_INF_F) ? 1 : 0;
            nl += (lkv[k] > -CUDART_INF_F) ? 1 : 0;
        }
        float ssum = s_ws[0] + s_ws[1] + s_ws[2] + s_ws[3];
        int np = nd * nl;
        g_losses[b] = (np > 0) ? (ssum / (float)np) : 0.f;

        // ============ Phase D: last loss CTA writes the scalar ==============
        __threadfence();
        unsigned old = atomicAdd(&g_done_cnt, 1u);
        if (old == (BB - 1)) {
            g_done_cnt = 0u;   // reset for replay
            __threadfence();
            float tot = 0.f;
            #pragma unroll
            for (int q = 0; q < BB; q++) tot += __ldcg(&g_losses[q]);
            out[0] = tot / (float)BB;
        }
    }
}

extern "C" void kernel_launch(void* const* d_in, const int* in_sizes, int n_in,
                              void* d_out, int out_size)
{
    const float* loc = (const float*)d_in[0];   // loc_features [8,256,128,128]
    const float* det = (const float*)d_in[1];   // det_features [8,256,128,128]
    float* out = (float*)d_out;

    fused_kernel<<<NMAPS * CTAS_PER_MAP, NTHREADS>>>(det, loc, out);
}

// round 4
// speedup vs baseline: 2.0613x; 2.0613x over previous
#include <cuda_runtime.h>
#include <math_constants.h>

#define BB 8
#define CC 256
#define HH 128
#define WW 128
#define HW (HH*WW)
#define TOPK 10
#define THRESH 0.5f
#define MARGIN 0.5f
#define EPSV 1e-8f
#define NMAPS 16
#define CAND_CAP 3072      // ~1850 expected strict 3x3 maxima; big margin

// scratch (no allocations allowed); counters self-reset -> replay-safe
__device__ float    g_intensity[NMAPS][HW];
__device__ float    g_topk_val[NMAPS][TOPK];
__device__ int      g_topk_idx[NMAPS][TOPK];
__device__ float    g_losses[BB];
__device__ unsigned g_samp_cnt[BB];
__device__ unsigned g_done_cnt;

// ---------------------------------------------------------------------------
// Kernel 1: intensity stream. 512 CTAs x 256 thr = 4096 warps (~27.7/SM).
// Channel dim split in half across the CTA: thread (half, gl) sums 128
// channels of float4 group g; halves combine via 2KB smem. 268MB HBM stream.
// ---------------------------------------------------------------------------
__global__ void __launch_bounds__(256) intensity_kernel(
    const float* __restrict__ det, const float* __restrict__ loc)
{
    __shared__ float4 s_part[128];

    const int bid  = blockIdx.x;          // 0..511
    const int m    = bid >> 5;            // map 0..15 (0..7 det, 8..15 loc)
    const int sl   = bid & 31;            // slice
    const int t    = m >> 3;
    const int b    = m & 7;
    const int tid  = threadIdx.x;
    const int half = tid >> 7;            // channel half
    const int gl   = tid & 127;
    const int g    = sl * 128 + gl;       // float4 group 0..4095

    const float* src = (t == 0) ? det : loc;
    const float4* base = ((const float4*)(src + (size_t)b * CC * HW))
                         + g + (size_t)half * 128 * (HW / 4);

    float a0 = 0.f, a1 = 0.f, a2 = 0.f, a3 = 0.f;
    #pragma unroll 8
    for (int c = 0; c < 128; c++) {
        float4 v = __ldcs(base + (size_t)c * (HW / 4));
        a0 = fmaf(v.x, v.x, a0);
        a1 = fmaf(v.y, v.y, a1);
        a2 = fmaf(v.z, v.z, a2);
        a3 = fmaf(v.w, v.w, a3);
    }
    if (half) s_part[gl] = make_float4(a0, a1, a2, a3);
    __syncthreads();
    if (!half) {
        float4 p = s_part[gl];
        float4 o;
        o.x = sqrtf(a0 + p.x);
        o.y = sqrtf(a1 + p.y);
        o.z = sqrtf(a2 + p.z);
        o.w = sqrtf(a3 + p.w);
        ((float4*)g_intensity[m])[g] = o;
    }
}

// ---------------------------------------------------------------------------
// Kernel 2: tail. 16 CTAs x 256 thr, 88KB dynamic smem.
// Per map: stage intensity in smem, 3x3 strict maxima -> candidate list,
// warp-0 top-10 (value desc, index asc = lax.top_k). Then counter-gated
// per-sample cosine loss and final scalar, all in this one launch.
// ---------------------------------------------------------------------------
extern __shared__ float smdyn[];
__global__ void __launch_bounds__(256) tail_kernel(
    const float* __restrict__ det, const float* __restrict__ loc,
    float* __restrict__ out)
{
    float* raw  = smdyn;                         // HW floats (64KB)
    float* cval = smdyn + HW;                    // CAND_CAP (12KB)
    int*   cidx = (int*)(smdyn + HW + CAND_CAP); // CAND_CAP (12KB)
    // loss-phase aliases over dead raw region:
    float (*df)[CC] = (float(*)[CC])smdyn;
    float (*lf)[CC] = (float(*)[CC])(smdyn + TOPK * CC);

    __shared__ unsigned s_flag;
    __shared__ int s_cn;
    __shared__ float s_na[TOPK], s_nb[TOPK], s_ws[8];

    const int tid = threadIdx.x;
    const int m   = blockIdx.x;       // 0..15
    const int b   = m & 7;

    // stage intensity (L2-resident, coalesced float4)
    {
        const float4* gi = (const float4*)g_intensity[m];
        for (int i = tid; i < HW / 4; i += 256)
            ((float4*)raw)[i] = __ldcg(&gi[i]);
        if (tid == 0) s_cn = 0;
    }
    __syncthreads();

    // 3x3 strict local maxima above threshold
    for (int i = tid; i < HW; i += 256) {
        float v = raw[i];
        if (v > THRESH) {
            int y = i >> 7, x = i & 127;
            bool peak = true;
            #pragma unroll
            for (int dy = -1; dy <= 1; dy++) {
                int yy = y + dy;
                if (yy < 0 || yy >= HH) continue;
                #pragma unroll
                for (int dx = -1; dx <= 1; dx++) {
                    int xx = x + dx;
                    if (xx < 0 || xx >= WW) continue;
                    if (raw[(yy << 7) + xx] > v) peak = false;
                }
            }
            if (peak) {
                int p = atomicAdd(&s_cn, 1);
                if (p < CAND_CAP) { cval[p] = v; cidx[p] = i; }
            }
        }
    }
    __syncthreads();

    // warp 0: 10 argmax passes over candidates
    if (tid < 32) {
        int n = min(s_cn, CAND_CAP);
        for (int k = 0; k < TOPK; k++) {
            float bv = -CUDART_INF_F; int bi = 0x7fffffff; int bp = -1;
            for (int p = tid; p < n; p += 32) {
                float v = cval[p]; int i = cidx[p];
                if (v > bv || (v == bv && i < bi)) { bv = v; bi = i; bp = p; }
            }
            #pragma unroll
            for (int o = 16; o > 0; o >>= 1) {
                float v2 = __shfl_down_sync(0xffffffffu, bv, o);
                int   i2 = __shfl_down_sync(0xffffffffu, bi, o);
                int   p2 = __shfl_down_sync(0xffffffffu, bp, o);
                if (v2 > bv || (v2 == bv && i2 < bi)) { bv = v2; bi = i2; bp = p2; }
            }
            bp = __shfl_sync(0xffffffffu, bp, 0);
            if (tid == 0) {
                g_topk_val[m][k] = bv;              // -inf when no candidate
                g_topk_idx[m][k] = (bp >= 0) ? bi : 0;
                if (bp >= 0) cval[bp] = -CUDART_INF_F;
            }
            __syncwarp();
        }
    }
    __syncthreads();
    if (tid == 0) {
        __threadfence();
        unsigned old = atomicAdd(&g_samp_cnt[b], 1u);
        if (old == 1u) g_samp_cnt[b] = 0u;          // reset for replay
        s_flag = (old == 1u);
    }
    __syncthreads();
    if (!s_flag) return;   // 2nd-finished map of each sample computes the loss

    // ============ cosine-sim loss for sample b ==============================
    __threadfence();
    float dkv[TOPK], lkv[TOPK];
    int   dki[TOPK], lki[TOPK];
    #pragma unroll
    for (int k = 0; k < TOPK; k++) {
        dkv[k] = __ldcg(&g_topk_val[b][k]);
        dki[k] = __ldcg(&g_topk_idx[b][k]);
        lkv[k] = __ldcg(&g_topk_val[8 + b][k]);
        lki[k] = __ldcg(&g_topk_idx[8 + b][k]);
    }
    __syncthreads();   // raw/cand smem dead before aliasing overwrite

    // gather features: thread = channel
    const size_t cb = (size_t)b * CC * HW + (size_t)tid * HW;
    #pragma unroll
    for (int k = 0; k < TOPK; k++) {
        df[k][tid] = __ldg(&det[cb + dki[k]]);
        lf[k][tid] = __ldg(&loc[cb + lki[k]]);
    }
    __syncthreads();

    const int lane = tid & 31, w = tid >> 5;   // 8 warps
    for (int k = w; k < TOPK; k += 8) {
        float sa = 0.f, sb = 0.f;
        for (int c = lane; c < CC; c += 32) {
            sa = fmaf(df[k][c], df[k][c], sa);
            sb = fmaf(lf[k][c], lf[k][c], sb);
        }
        #pragma unroll
        for (int o = 16; o > 0; o >>= 1) {
            sa += __shfl_down_sync(0xffffffffu, sa, o);
            sb += __shfl_down_sync(0xffffffffu, sb, o);
        }
        if (lane == 0) {
            s_na[k] = fmaxf(sqrtf(sa), EPSV);
            s_nb[k] = fmaxf(sqrtf(sb), EPSV);
        }
    }
    __syncthreads();

    float lsum = 0.f;
    for (int p = w; p < TOPK * TOPK; p += 8) {
        int i = p / TOPK, j = p % TOPK;
        float dot = 0.f;
        for (int c = lane; c < CC; c += 32) dot = fmaf(df[i][c], lf[j][c], dot);
        #pragma unroll
        for (int o = 16; o > 0; o >>= 1)
            dot += __shfl_down_sync(0xffffffffu, dot, o);
        if (lane == 0 && dkv[i] > -CUDART_INF_F && lkv[j] > -CUDART_INF_F)
            lsum += fmaxf(dot / (s_na[i] * s_nb[j]) - MARGIN, 0.f);
    }
    if (lane == 0) s_ws[w] = lsum;
    __syncthreads();

    if (tid == 0) {
        int nd = 0, nl = 0;
        #pragma unroll
        for (int k = 0; k < TOPK; k++) {
            nd += (dkv[k] > -CUDART_INF_F) ? 1 : 0;
            nl += (lkv[k] > -CUDART_INF_F) ? 1 : 0;
        }
        float ssum = 0.f;
        #pragma unroll
        for (int q = 0; q < 8; q++) ssum += s_ws[q];
        int np = nd * nl;
        g_losses[b] = (np > 0) ? (ssum / (float)np) : 0.f;

        // last loss CTA writes the scalar (fixed-order sum, deterministic)
        __threadfence();
        unsigned old = atomicAdd(&g_done_cnt, 1u);
        if (old == (BB - 1)) {
            g_done_cnt = 0u;   // reset for replay
            __threadfence();
            float tot = 0.f;
            #pragma unroll
            for (int q = 0; q < BB; q++) tot += __ldcg(&g_losses[q]);
            out[0] = tot / (float)BB;
        }
    }
}

extern "C" void kernel_launch(void* const* d_in, const int* in_sizes, int n_in,
                              void* d_out, int out_size)
{
    const float* loc = (const float*)d_in[0];   // loc_features [8,256,128,128]
    const float* det = (const float*)d_in[1];   // det_features [8,256,128,128]
    float* out = (float*)d_out;

    intensity_kernel<<<512, 256>>>(det, loc);

    const int smem = (HW + 2 * CAND_CAP) * (int)sizeof(float);   // 88KB
    cudaFuncSetAttribute(tail_kernel,
                         cudaFuncAttributeMaxDynamicSharedMemorySize, smem);
    tail_kernel<<<NMAPS, 256, smem>>>(det, loc, out);
}

// round 5
// speedup vs baseline: 2.4599x; 1.1934x over previous
#include <cuda_runtime.h>
#include <math_constants.h>

#define BB 8
#define CC 256
#define HH 128
#define WW 128
#define HW (HH*WW)
#define TOPK 10
#define THRESH 0.5f
#define MARGIN 0.5f
#define EPSV 1e-8f
#define NMAPS 16
#define PAD 130                 // padded row pitch (-inf border, no branches)
#define RAWSZ (PAD*PAD)
#define TAILTHR 1024

// scratch (no allocations allowed); counters self-reset -> replay-safe
__device__ float    g_intensity[NMAPS][HW];
__device__ float    g_topk_val[NMAPS][TOPK];
__device__ int      g_topk_idx[NMAPS][TOPK];
__device__ float    g_losses[BB];
__device__ unsigned g_samp_cnt[BB];
__device__ unsigned g_done_cnt;

// ---------------------------------------------------------------------------
// Kernel 1: intensity stream (UNCHANGED from R4 — measured 7.1 TB/s, 89% of
// HBM spec). 512 CTAs x 256 thr; channel dim split in half across the CTA.
// ---------------------------------------------------------------------------
__global__ void __launch_bounds__(256) intensity_kernel(
    const float* __restrict__ det, const float* __restrict__ loc)
{
    __shared__ float4 s_part[128];

    const int bid  = blockIdx.x;
    const int m    = bid >> 5;
    const int sl   = bid & 31;
    const int t    = m >> 3;
    const int b    = m & 7;
    const int tid  = threadIdx.x;
    const int half = tid >> 7;
    const int gl   = tid & 127;
    const int g    = sl * 128 + gl;

    const float* src = (t == 0) ? det : loc;
    const float4* base = ((const float4*)(src + (size_t)b * CC * HW))
                         + g + (size_t)half * 128 * (HW / 4);

    float a0 = 0.f, a1 = 0.f, a2 = 0.f, a3 = 0.f;
    #pragma unroll 8
    for (int c = 0; c < 128; c++) {
        float4 v = __ldcs(base + (size_t)c * (HW / 4));
        a0 = fmaf(v.x, v.x, a0);
        a1 = fmaf(v.y, v.y, a1);
        a2 = fmaf(v.z, v.z, a2);
        a3 = fmaf(v.w, v.w, a3);
    }
    if (half) s_part[gl] = make_float4(a0, a1, a2, a3);
    __syncthreads();
    if (!half) {
        float4 p = s_part[gl];
        float4 o;
        o.x = sqrtf(a0 + p.x);
        o.y = sqrtf(a1 + p.y);
        o.z = sqrtf(a2 + p.z);
        o.w = sqrtf(a3 + p.w);
        ((float4*)g_intensity[m])[g] = o;
    }
}

// ---------------------------------------------------------------------------
// Kernel 2: tail. 16 CTAs x 1024 thr, ~130KB dyn smem.
// Padded map -> branch-free 3x3 strict maxima; hierarchical exact top-10
// (32 per-warp top-10s merged by warp 0); counter-gated loss + final scalar.
// ---------------------------------------------------------------------------
extern __shared__ float smdyn[];
__global__ void __launch_bounds__(TAILTHR) tail_kernel(
    const float* __restrict__ det, const float* __restrict__ loc,
    float* __restrict__ out)
{
    float* rawp   = smdyn;            // RAWSZ floats, padded 130x130
    float* masked = smdyn + RAWSZ;    // HW floats
    // loss-phase aliases (rawp dead by then):
    float (*df)[CC] = (float(*)[CC])smdyn;
    float (*lf)[CC] = (float(*)[CC])(smdyn + TOPK * CC);

    __shared__ float s_wval[32][TOPK];
    __shared__ int   s_widx[32][TOPK];
    __shared__ float s_na[TOPK], s_nb[TOPK], s_ws[32];
    __shared__ float s_dkv[TOPK], s_lkv[TOPK];
    __shared__ int   s_dki[TOPK], s_lki[TOPK];
    __shared__ unsigned s_flag;

    const int tid  = threadIdx.x;
    const int lane = tid & 31;
    const int w    = tid >> 5;        // 32 warps
    const int m    = blockIdx.x;      // 0..15
    const int b    = m & 7;

    // ---- stage intensity into padded smem (border = -inf) ------------------
    for (int i = tid; i < RAWSZ; i += TAILTHR) rawp[i] = -CUDART_INF_F;
    __syncthreads();
    {
        const float* gi = g_intensity[m];
        for (int i = tid; i < HW; i += TAILTHR) {
            int y = i >> 7, x = i & 127;
            rawp[(y + 1) * PAD + (x + 1)] = __ldcg(&gi[i]);
        }
    }
    __syncthreads();

    // ---- branch-free 3x3 strict maxima -> masked map -----------------------
    for (int i = tid; i < HW; i += TAILTHR) {
        int y = i >> 7, x = i & 127;
        const float* c = &rawp[(y + 1) * PAD + (x + 1)];
        float v = c[0];
        float n0 = fmaxf(fmaxf(c[-PAD - 1], c[-PAD]), c[-PAD + 1]);
        float n1 = fmaxf(c[-1], c[1]);
        float n2 = fmaxf(fmaxf(c[PAD - 1], c[PAD]), c[PAD + 1]);
        float nmax = fmaxf(fmaxf(n0, n1), n2);
        masked[i] = (v > THRESH && v >= nmax) ? v : -CUDART_INF_F;
    }
    __syncthreads();

    // ---- per-warp top-10 over its 512-pixel slice ---------------------------
    {
        const int base = w * 512;
        for (int k = 0; k < TOPK; k++) {
            float bv = -CUDART_INF_F; int bi = 0x7fffffff;
            #pragma unroll
            for (int q = 0; q < 16; q++) {
                int i = base + q * 32 + lane;
                float v = masked[i];
                if (v > bv || (v == bv && i < bi)) { bv = v; bi = i; }
            }
            #pragma unroll
            for (int o = 16; o > 0; o >>= 1) {
                float v2 = __shfl_down_sync(0xffffffffu, bv, o);
                int   i2 = __shfl_down_sync(0xffffffffu, bi, o);
                if (v2 > bv || (v2 == bv && i2 < bi)) { bv = v2; bi = i2; }
            }
            bv = __shfl_sync(0xffffffffu, bv, 0);
            bi = __shfl_sync(0xffffffffu, bi, 0);
            if (lane == 0) {
                s_wval[w][k] = bv;
                s_widx[w][k] = bi;
                if (bv > -CUDART_INF_F) masked[bi] = -CUDART_INF_F;
            }
            __syncwarp();
        }
    }
    __syncthreads();

    // ---- warp 0 merges 320 survivors (val desc, idx asc = lax.top_k) -------
    if (w == 0) {
        float* fv = &s_wval[0][0];   // 320 contiguous
        int*   fi = &s_widx[0][0];
        for (int k = 0; k < TOPK; k++) {
            float bv = -CUDART_INF_F; int bi = 0x7fffffff; int bp = -1;
            #pragma unroll
            for (int q = 0; q < 10; q++) {
                int p = q * 32 + lane;
                float v = fv[p]; int i = fi[p];
                if (v > bv || (v == bv && i < bi)) { bv = v; bi = i; bp = p; }
            }
            #pragma unroll
            for (int o = 16; o > 0; o >>= 1) {
                float v2 = __shfl_down_sync(0xffffffffu, bv, o);
                int   i2 = __shfl_down_sync(0xffffffffu, bi, o);
                int   p2 = __shfl_down_sync(0xffffffffu, bp, o);
                if (v2 > bv || (v2 == bv && i2 < bi)) { bv = v2; bi = i2; bp = p2; }
            }
            bp = __shfl_sync(0xffffffffu, bp, 0);
            if (lane == 0) {
                g_topk_val[m][k] = bv;                 // -inf when absent
                g_topk_idx[m][k] = (bv > -CUDART_INF_F) ? bi : 0;
                if (bp >= 0) fv[bp] = -CUDART_INF_F;
            }
            __syncwarp();
        }
    }
    __syncthreads();
    if (tid == 0) {
        __threadfence();
        unsigned old = atomicAdd(&g_samp_cnt[b], 1u);
        if (old == 1u) g_samp_cnt[b] = 0u;             // reset for replay
        s_flag = (old == 1u);
    }
    __syncthreads();
    if (!s_flag) return;   // 2nd-finished map of each sample computes the loss

    // ============ cosine-sim loss for sample b ==============================
    __threadfence();
    if (tid < TOPK) {
        s_dkv[tid] = __ldcg(&g_topk_val[b][tid]);
        s_dki[tid] = __ldcg(&g_topk_idx[b][tid]);
        s_lkv[tid] = __ldcg(&g_topk_val[8 + b][tid]);
        s_lki[tid] = __ldcg(&g_topk_idx[8 + b][tid]);
    }
    __syncthreads();   // also: smem candidate data dead before alias overwrite

    // gather features [10][256] x2 (5 loads/thread, scattered DRAM, MLP=5)
    {
        const float* dbase = det + (size_t)b * CC * HW;
        const float* lbase = loc + (size_t)b * CC * HW;
        for (int idx = tid; idx < TOPK * CC; idx += TAILTHR) {
            int k = idx >> 8, c = idx & 255;
            df[k][c] = __ldg(&dbase[(size_t)c * HW + s_dki[k]]);
            lf[k][c] = __ldg(&lbase[(size_t)c * HW + s_lki[k]]);
        }
    }
    __syncthreads();

    // norms: warp k handles row k
    if (w < TOPK) {
        float sa = 0.f, sb = 0.f;
        #pragma unroll
        for (int c = lane; c < CC; c += 32) {
            sa = fmaf(df[w][c], df[w][c], sa);
            sb = fmaf(lf[w][c], lf[w][c], sb);
        }
        #pragma unroll
        for (int o = 16; o > 0; o >>= 1) {
            sa += __shfl_down_sync(0xffffffffu, sa, o);
            sb += __shfl_down_sync(0xffffffffu, sb, o);
        }
        if (lane == 0) {
            s_na[w] = fmaxf(sqrtf(sa), EPSV);
            s_nb[w] = fmaxf(sqrtf(sb), EPSV);
        }
    }
    __syncthreads();

    // 100 pair dots over 32 warps
    float lsum = 0.f;
    for (int p = w; p < TOPK * TOPK; p += 32) {
        int i = p / TOPK, j = p % TOPK;
        float dot = 0.f;
        #pragma unroll
        for (int c = lane; c < CC; c += 32) dot = fmaf(df[i][c], lf[j][c], dot);
        #pragma unroll
        for (int o = 16; o > 0; o >>= 1)
            dot += __shfl_down_sync(0xffffffffu, dot, o);
        if (lane == 0 && s_dkv[i] > -CUDART_INF_F && s_lkv[j] > -CUDART_INF_F)
            lsum += fmaxf(dot / (s_na[i] * s_nb[j]) - MARGIN, 0.f);
    }
    if (lane == 0) s_ws[w] = lsum;
    __syncthreads();

    if (tid == 0) {
        int nd = 0, nl = 0;
        #pragma unroll
        for (int k = 0; k < TOPK; k++) {
            nd += (s_dkv[k] > -CUDART_INF_F) ? 1 : 0;
            nl += (s_lkv[k] > -CUDART_INF_F) ? 1 : 0;
        }
        float ssum = 0.f;
        #pragma unroll
        for (int q = 0; q < 32; q++) ssum += s_ws[q];
        int np = nd * nl;
        g_losses[b] = (np > 0) ? (ssum / (float)np) : 0.f;

        // last loss CTA writes the scalar (fixed-order sum, deterministic)
        __threadfence();
        unsigned old = atomicAdd(&g_done_cnt, 1u);
        if (old == (BB - 1)) {
            g_done_cnt = 0u;   // reset for replay
            __threadfence();
            float tot = 0.f;
            #pragma unroll
            for (int q = 0; q < BB; q++) tot += __ldcg(&g_losses[q]);
            out[0] = tot / (float)BB;
        }
    }
}

extern "C" void kernel_launch(void* const* d_in, const int* in_sizes, int n_in,
                              void* d_out, int out_size)
{
    const float* loc = (const float*)d_in[0];   // loc_features [8,256,128,128]
    const float* det = (const float*)d_in[1];   // det_features [8,256,128,128]
    float* out = (float*)d_out;

    intensity_kernel<<<512, 256>>>(det, loc);

    const int smem = (RAWSZ + HW) * (int)sizeof(float);   // ~130KB
    cudaFuncSetAttribute(tail_kernel,
                         cudaFuncAttributeMaxDynamicSharedMemorySize, smem);
    tail_kernel<<<NMAPS, TAILTHR, smem>>>(det, loc, out);
}

// round 6
// speedup vs baseline: 2.4608x; 1.0004x over previous
#include <cuda_runtime.h>
#include <math_constants.h>

#define BB 8
#define CC 256
#define HH 128
#define WW 128
#define HW (HH*WW)
#define TOPK 10
#define THRESH 0.5f
#define MARGIN 0.5f
#define EPSV 1e-8f
#define NMAPS 16
#define JCTAS 8                    // tail CTAs per map
#define JROWS 16                   // rows per tail CTA
#define JPIX (JROWS*WW)            // 2048 pixels per tail CTA
#define PADW 130
#define STG_ROWS 18                // 16 rows + halo
#define T2 256

// scratch (no allocations allowed); counters self-reset -> replay-safe
__device__ float    g_intensity[NMAPS][HW];
__device__ float    g_part_val[NMAPS][JCTAS][TOPK];
__device__ int      g_part_idx[NMAPS][JCTAS][TOPK];
__device__ float    g_losses[BB];
__device__ unsigned g_samp_cnt[BB];
__device__ unsigned g_done_cnt;

// ---------------------------------------------------------------------------
// Kernel 1: intensity stream (UNCHANGED — measured 6.6TB/s, ~85% HBM).
// ---------------------------------------------------------------------------
__global__ void __launch_bounds__(256) intensity_kernel(
    const float* __restrict__ det, const float* __restrict__ loc)
{
    __shared__ float4 s_part[128];

    const int bid  = blockIdx.x;
    const int m    = bid >> 5;
    const int sl   = bid & 31;
    const int t    = m >> 3;
    const int b    = m & 7;
    const int tid  = threadIdx.x;
    const int half = tid >> 7;
    const int gl   = tid & 127;
    const int g    = sl * 128 + gl;

    const float* src = (t == 0) ? det : loc;
    const float4* base = ((const float4*)(src + (size_t)b * CC * HW))
                         + g + (size_t)half * 128 * (HW / 4);

    float a0 = 0.f, a1 = 0.f, a2 = 0.f, a3 = 0.f;
    #pragma unroll 8
    for (int c = 0; c < 128; c++) {
        float4 v = __ldcs(base + (size_t)c * (HW / 4));
        a0 = fmaf(v.x, v.x, a0);
        a1 = fmaf(v.y, v.y, a1);
        a2 = fmaf(v.z, v.z, a2);
        a3 = fmaf(v.w, v.w, a3);
    }
    if (half) s_part[gl] = make_float4(a0, a1, a2, a3);
    __syncthreads();
    if (!half) {
        float4 p = s_part[gl];
        float4 o;
        o.x = sqrtf(a0 + p.x);
        o.y = sqrtf(a1 + p.y);
        o.z = sqrtf(a2 + p.z);
        o.w = sqrtf(a3 + p.w);
        ((float4*)g_intensity[m])[g] = o;
    }
}

// ---------------------------------------------------------------------------
// Kernel 2: tail, 128 CTAs x 256 thr. CTA (m,j) owns 16 rows of map m:
// halo-staged branch-free 3x3 maxima, hierarchical exact top-10 -> g_part.
// Last CTA per sample (counter=16) merges partials, gathers features,
// computes the loss; last loss CTA writes the final scalar.
// ---------------------------------------------------------------------------
__global__ void __launch_bounds__(T2) tail_kernel(
    const float* __restrict__ det, const float* __restrict__ loc,
    float* __restrict__ out)
{
    __shared__ float sbuf[5120];                  // 20KB, phase-aliased
    float* rawp   = sbuf;                         // STG_ROWS*PADW = 2340
    float* masked = sbuf + 2560;                  // JPIX = 2048
    float (*df)[CC] = (float(*)[CC])sbuf;         // loss alias: 2560
    float (*lf)[CC] = (float(*)[CC])(sbuf + 2560);// loss alias: 2560

    __shared__ float s_wval[8][TOPK];
    __shared__ int   s_widx[8][TOPK];
    __shared__ float s_mv[2][JCTAS * TOPK];
    __shared__ int   s_mi[2][JCTAS * TOPK];
    __shared__ float s_dkv[TOPK], s_lkv[TOPK];
    __shared__ int   s_dki[TOPK], s_lki[TOPK];
    __shared__ float s_na[TOPK], s_nb[TOPK], s_ws[8];
    __shared__ unsigned s_flag;

    const int tid  = threadIdx.x;
    const int lane = tid & 31;
    const int w    = tid >> 5;                    // 8 warps
    const int m    = blockIdx.x >> 3;             // map 0..15
    const int j    = blockIdx.x & 7;              // region within map
    const int b    = m & 7;

    // ---- stage 16 rows + halo into padded smem (-inf border) ---------------
    for (int i = tid; i < STG_ROWS * PADW; i += T2) rawp[i] = -CUDART_INF_F;
    __syncthreads();
    {
        const float* gi = g_intensity[m];
        for (int i = tid; i < STG_ROWS * WW; i += T2) {
            int r = i >> 7, x = i & 127;
            int grow = j * JROWS - 1 + r;
            if (grow >= 0 && grow < HH)
                rawp[r * PADW + x + 1] = __ldcg(&gi[(grow << 7) + x]);
        }
    }
    __syncthreads();

    // ---- branch-free 3x3 strict maxima over 2048 local pixels --------------
    for (int p = tid; p < JPIX; p += T2) {
        int yl = p >> 7, x = p & 127;
        const float* c = &rawp[(yl + 1) * PADW + (x + 1)];
        float v = c[0];
        float n0 = fmaxf(fmaxf(c[-PADW - 1], c[-PADW]), c[-PADW + 1]);
        float n1 = fmaxf(c[-1], c[1]);
        float n2 = fmaxf(fmaxf(c[PADW - 1], c[PADW]), c[PADW + 1]);
        float nmax = fmaxf(fmaxf(n0, n1), n2);
        masked[p] = (v > THRESH && v >= nmax) ? v : -CUDART_INF_F;
    }
    __syncthreads();

    // ---- per-warp top-10 over its 256-pixel slice (local idx = global-256j) -
    {
        const int base = w * 256;
        for (int k = 0; k < TOPK; k++) {
            float bv = -CUDART_INF_F; int bp = 0x7fffffff;
            #pragma unroll
            for (int q = 0; q < 8; q++) {
                int p = base + q * 32 + lane;
                float v = masked[p];
                if (v > bv || (v == bv && p < bp)) { bv = v; bp = p; }
            }
            #pragma unroll
            for (int o = 16; o > 0; o >>= 1) {
                float v2 = __shfl_down_sync(0xffffffffu, bv, o);
                int   p2 = __shfl_down_sync(0xffffffffu, bp, o);
                if (v2 > bv || (v2 == bv && p2 < bp)) { bv = v2; bp = p2; }
            }
            bv = __shfl_sync(0xffffffffu, bv, 0);
            bp = __shfl_sync(0xffffffffu, bp, 0);
            if (lane == 0) {
                s_wval[w][k] = bv;
                s_widx[w][k] = j * JPIX + bp;      // global pixel index
                masked[bp] = -CUDART_INF_F;
            }
            __syncwarp();
        }
    }
    __syncthreads();

    // ---- warp 0 merges 80 -> region top-10 -> g_part ------------------------
    if (w == 0) {
        float* fv = &s_wval[0][0];
        int*   fi = &s_widx[0][0];
        for (int k = 0; k < TOPK; k++) {
            float bv = -CUDART_INF_F; int bi = 0x7fffffff; int bp = -1;
            #pragma unroll
            for (int q = 0; q < 3; q++) {
                int p = q * 32 + lane;
                if (p < 80) {
                    float v = fv[p]; int i = fi[p];
                    if (v > bv || (v == bv && i < bi)) { bv = v; bi = i; bp = p; }
                }
            }
            #pragma unroll
            for (int o = 16; o > 0; o >>= 1) {
                float v2 = __shfl_down_sync(0xffffffffu, bv, o);
                int   i2 = __shfl_down_sync(0xffffffffu, bi, o);
                int   p2 = __shfl_down_sync(0xffffffffu, bp, o);
                if (v2 > bv || (v2 == bv && i2 < bi)) { bv = v2; bi = i2; bp = p2; }
            }
            bp = __shfl_sync(0xffffffffu, bp, 0);
            if (lane == 0) {
                g_part_val[m][j][k] = bv;
                g_part_idx[m][j][k] = bi;
                if (bp >= 0) fv[bp] = -CUDART_INF_F;
            }
            __syncwarp();
        }
    }
    __syncthreads();
    if (tid == 0) {
        __threadfence();
        unsigned old = atomicAdd(&g_samp_cnt[b], 1u);
        if (old == 15u) g_samp_cnt[b] = 0u;        // reset for replay
        s_flag = (old == 15u);
    }
    __syncthreads();
    if (!s_flag) return;   // last of the sample's 16 CTAs computes the loss

    // ---- merge 80 partials per map: warp0 = det(map b), warp1 = loc(8+b) ---
    __threadfence();
    if (w < 2) {
        const int mm = (w == 0) ? b : (8 + b);
        const float* pv = &g_part_val[mm][0][0];
        const int*   pi = &g_part_idx[mm][0][0];
        for (int p = lane; p < 80; p += 32) {
            s_mv[w][p] = __ldcg(&pv[p]);
            s_mi[w][p] = __ldcg(&pi[p]);
        }
        __syncwarp();
        for (int k = 0; k < TOPK; k++) {
            float bv = -CUDART_INF_F; int bi = 0x7fffffff; int bp = -1;
            #pragma unroll
            for (int q = 0; q < 3; q++) {
                int p = q * 32 + lane;
                if (p < 80) {
                    float v = s_mv[w][p]; int i = s_mi[w][p];
                    if (v > bv || (v == bv && i < bi)) { bv = v; bi = i; bp = p; }
                }
            }
            #pragma unroll
            for (int o = 16; o > 0; o >>= 1) {
                float v2 = __shfl_down_sync(0xffffffffu, bv, o);
                int   i2 = __shfl_down_sync(0xffffffffu, bi, o);
                int   p2 = __shfl_down_sync(0xffffffffu, bp, o);
                if (v2 > bv || (v2 == bv && i2 < bi)) { bv = v2; bi = i2; bp = p2; }
            }
            bp = __shfl_sync(0xffffffffu, bp, 0);
            if (lane == 0) {
                if (w == 0) { s_dkv[k] = bv; s_dki[k] = (bv > -CUDART_INF_F) ? bi : 0; }
                else        { s_lkv[k] = bv; s_lki[k] = (bv > -CUDART_INF_F) ? bi : 0; }
                if (bp >= 0) s_mv[w][bp] = -CUDART_INF_F;
            }
            __syncwarp();
        }
    }
    __syncthreads();   // also: sbuf detection data dead before alias overwrite

    // ---- gather features [10][256] x2 (20 scattered loads/thread) ----------
    {
        const float* dbase = det + (size_t)b * CC * HW;
        const float* lbase = loc + (size_t)b * CC * HW;
        for (int idx = tid; idx < TOPK * CC; idx += T2) {
            int k = idx >> 8, c = idx & 255;
            df[k][c] = __ldg(&dbase[(size_t)c * HW + s_dki[k]]);
            lf[k][c] = __ldg(&lbase[(size_t)c * HW + s_lki[k]]);
        }
    }
    __syncthreads();

    // ---- norms (warp-per-row) ----------------------------------------------
    for (int k = w; k < TOPK; k += 8) {
        float sa = 0.f, sb = 0.f;
        #pragma unroll
        for (int c = lane; c < CC; c += 32) {
            sa = fmaf(df[k][c], df[k][c], sa);
            sb = fmaf(lf[k][c], lf[k][c], sb);
        }
        #pragma unroll
        for (int o = 16; o > 0; o >>= 1) {
            sa += __shfl_down_sync(0xffffffffu, sa, o);
            sb += __shfl_down_sync(0xffffffffu, sb, o);
        }
        if (lane == 0) {
            s_na[k] = fmaxf(sqrtf(sa), EPSV);
            s_nb[k] = fmaxf(sqrtf(sb), EPSV);
        }
    }
    __syncthreads();

    // ---- 100 pair dots over 8 warps ----------------------------------------
    float lsum = 0.f;
    for (int p = w; p < TOPK * TOPK; p += 8) {
        int i = p / TOPK, jj = p % TOPK;
        float dot = 0.f;
        #pragma unroll
        for (int c = lane; c < CC; c += 32) dot = fmaf(df[i][c], lf[jj][c], dot);
        #pragma unroll
        for (int o = 16; o > 0; o >>= 1)
            dot += __shfl_down_sync(0xffffffffu, dot, o);
        if (lane == 0 && s_dkv[i] > -CUDART_INF_F && s_lkv[jj] > -CUDART_INF_F)
            lsum += fmaxf(dot / (s_na[i] * s_nb[jj]) - MARGIN, 0.f);
    }
    if (lane == 0) s_ws[w] = lsum;
    __syncthreads();

    if (tid == 0) {
        int nd = 0, nl = 0;
        #pragma unroll
        for (int k = 0; k < TOPK; k++) {
            nd += (s_dkv[k] > -CUDART_INF_F) ? 1 : 0;
            nl += (s_lkv[k] > -CUDART_INF_F) ? 1 : 0;
        }
        float ssum = 0.f;
        #pragma unroll
        for (int q = 0; q < 8; q++) ssum += s_ws[q];
        int np = nd * nl;
        g_losses[b] = (np > 0) ? (ssum / (float)np) : 0.f;

        // last loss CTA writes the scalar (fixed-order, deterministic)
        __threadfence();
        unsigned old = atomicAdd(&g_done_cnt, 1u);
        if (old == (BB - 1)) {
            g_done_cnt = 0u;   // reset for replay
            __threadfence();
            float tot = 0.f;
            #pragma unroll
            for (int q = 0; q < BB; q++) tot += __ldcg(&g_losses[q]);
            out[0] = tot / (float)BB;
        }
    }
}

extern "C" void kernel_launch(void* const* d_in, const int* in_sizes, int n_in,
                              void* d_out, int out_size)
{
    const float* loc = (const float*)d_in[0];   // loc_features [8,256,128,128]
    const float* det = (const float*)d_in[1];   // det_features [8,256,128,128]
    float* out = (float*)d_out;

    intensity_kernel<<<512, 256>>>(det, loc);
    tail_kernel<<<NMAPS * JCTAS, T2>>>(det, loc, out);
}